// round 16
// baseline (speedup 1.0000x reference)
#include <cuda_runtime.h>
#include <cuda_bf16.h>
#include <cstdint>

// ---------------------------------------------------------------------------
// MultiheadChannelAttention — R15: score_mma 2-term (single-bf16 K; softmax
// absorbs absolute logit error), v_transpose eliminated via ldmatrix.trans
// (dwconv writes split-bf16 V in [c][pix]; pv loads A-frags transposed).
// ---------------------------------------------------------------------------

namespace {
constexpr int B = 8, C = 128, H = 128, W = 128;
constexpr int HW = 16384;
constexpr int NH = 8;
constexpr int D = HW / NH;     // 2048
constexpr float SCALE = 1.0f / 128.0f;

// pv tiles: 272B rows (128 + 8 pad bf16)
constexpr int LDT_B = 272;
constexpr int TILE_B2 = 128 * LDT_B;        // 34816
constexpr int SA_H = 0;
constexpr int SA_L = TILE_B2;
constexpr int SB_H = 2 * TILE_B2;
constexpr int SB_L = 3 * TILE_B2;
constexpr int SMEM_PV = 4 * TILE_B2;        // 139264

// score tiles: 144B rows (64 bf16 + 8 pad), 64 rows each; 3 tiles/chunk,
// double buffered
constexpr int LDT_S = 144;
constexpr int SCT = 64 * LDT_S;             // 9216 per tile
constexpr int SCB = 3 * SCT;                // 27648 per buffer
constexpr int SMEM_SCORE = 2 * SCB;         // 55296

// out_conv pipeline: per-buffer 4 tiles of 128 rows x 144B
constexpr int OC_TILE = 128 * LDT_S;        // 18432
constexpr int OC_BUF = 4 * OC_TILE;         // 73728
constexpr int SMEM_OC = 2 * OC_BUF;         // 147456
}

typedef unsigned long long u64;

// Scratch (device globals: no allocation allowed)
__device__ __nv_bfloat16 g_qh[(size_t)B * C * HW];
__device__ __nv_bfloat16 g_ql[(size_t)B * C * HW];
__device__ __nv_bfloat16 g_kh[(size_t)B * C * HW];
__device__ __nv_bfloat16 g_vh[(size_t)B * C * HW];   // V split bf16 [b][c][pix]
__device__ __nv_bfloat16 g_vl[(size_t)B * C * HW];
__device__ float g_s[B * NH * C * C];                // scores (fp32)
__device__ __nv_bfloat16 g_ph[B * NH * C * C];       // softmax probs split
__device__ __nv_bfloat16 g_pl[B * NH * C * C];
__device__ __nv_bfloat16 g_ah[(size_t)B * HW * C];   // attn out [b][pix][ci]
__device__ __nv_bfloat16 g_al[(size_t)B * HW * C];
__device__ __nv_bfloat16 g_wh[9 * C * C];            // wo split [tap][co][ci]
__device__ __nv_bfloat16 g_wl[9 * C * C];

// ---------------- helpers ---------------------------------------------------
__device__ __forceinline__ uint32_t smem_u32(const void* p) {
    uint32_t a;
    asm("{ .reg .u64 t; cvta.to.shared.u64 t, %1; cvt.u32.u64 %0, t; }" : "=r"(a) : "l"(p));
    return a;
}

__device__ __forceinline__ void cp16(uint32_t dst, const void* src, bool ok) {
    int sz = ok ? 16 : 0;
    asm volatile("cp.async.cg.shared.global [%0], [%1], 16, %2;"
                 :: "r"(dst), "l"(src), "r"(sz) : "memory");
}
#define CP_COMMIT() asm volatile("cp.async.commit_group;" ::: "memory")

#define LDSM4(r, addr)                                                          \
    asm volatile("ldmatrix.sync.aligned.m8n8.x4.shared.b16 {%0,%1,%2,%3}, [%4];" \
        : "=r"((r)[0]), "=r"((r)[1]), "=r"((r)[2]), "=r"((r)[3]) : "r"(addr))

#define LDSM4_T(r, addr)                                                        \
    asm volatile("ldmatrix.sync.aligned.m8n8.x4.trans.shared.b16 {%0,%1,%2,%3}, [%4];" \
        : "=r"((r)[0]), "=r"((r)[1]), "=r"((r)[2]), "=r"((r)[3]) : "r"(addr))

#define MMA_BF16(d, a, b0, b1)                                                  \
    asm volatile("mma.sync.aligned.m16n8k16.row.col.f32.bf16.bf16.f32 "         \
        "{%0,%1,%2,%3}, {%4,%5,%6,%7}, {%8,%9}, {%0,%1,%2,%3};"                 \
        : "+f"((d)[0]), "+f"((d)[1]), "+f"((d)[2]), "+f"((d)[3])                \
        : "r"((a)[0]), "r"((a)[1]), "r"((a)[2]), "r"((a)[3]), "r"(b0), "r"(b1))

union Pack8 { uint4 u; __nv_bfloat16 h[8]; };
union Pack2 { uint32_t u; __nv_bfloat16 h[2]; };

// ---------------------------------------------------------------------------
// Split wo [co][ci][tap] -> g_wh/g_wl [tap][co][ci] (bf16 hi/lo)
// ---------------------------------------------------------------------------
__global__ void prep_w(const float* __restrict__ wo) {
    int i = blockIdx.x * 256 + threadIdx.x;
    if (i >= C * C * 9) return;
    int co = i / (C * 9);
    int rem = i % (C * 9);
    int ci = rem / 9;
    int tap = rem % 9;
    float w = wo[i];
    __nv_bfloat16 hi = __float2bfloat16(w);
    __nv_bfloat16 lo = __float2bfloat16(w - __bfloat162float(hi));
    int dst = tap * (C * C) + co * C + ci;
    g_wh[dst] = hi;
    g_wl[dst] = lo;
}

// ---------------------------------------------------------------------------
// Fused q/k/v depthwise 9x9 conv (pad 4). Q split bf16, K hi-only,
// V split bf16 (all [b][c][pix]).
// ---------------------------------------------------------------------------
__global__ void __launch_bounds__(256) qkv_dwconv(
        const float* __restrict__ x,
        const float* __restrict__ wq, const float* __restrict__ bq,
        const float* __restrict__ wk, const float* __restrict__ bk,
        const float* __restrict__ wv, const float* __restrict__ bv) {
    __shared__ float tile[40][72];
    __shared__ float wsm[3][81];

    int bc = blockIdx.z;
    int b = bc >> 7, c = bc & 127;
    int x0 = blockIdx.x * 64, y0 = blockIdx.y * 32;
    int tid = threadIdx.x;
    int lane = tid & 7;
    int r = tid >> 3;

    if (tid < 243) {
        int c3 = tid / 81, t = tid % 81;
        const float* wsrc = (c3 == 0) ? wq : (c3 == 1) ? wk : wv;
        wsm[c3][t] = wsrc[c * 81 + t];
    }
    const float* xp = x + (size_t)(b * C + c) * HW;
    for (int i = tid; i < 40 * 72; i += 256) {
        int tr = i / 72, tc = i % 72;
        int gy = y0 - 4 + tr, gx = x0 - 4 + tc;
        float v = 0.0f;
        if ((unsigned)gy < (unsigned)H && (unsigned)gx < (unsigned)W)
            v = xp[gy * W + gx];
        tile[tr][tc] = v;
    }
    __syncthreads();

    float aq[8], ak[8], av[8];
    float biasq = bq[c], biask = bk[c], biasv = bv[c];
#pragma unroll
    for (int p = 0; p < 8; p++) { aq[p] = biasq; ak[p] = biask; av[p] = biasv; }

#pragma unroll
    for (int ky = 0; ky < 9; ky++) {
        float win[16];
        float4 u0 = *(const float4*)&tile[r + ky][lane * 8];
        float4 u1 = *(const float4*)&tile[r + ky][lane * 8 + 4];
        float4 u2 = *(const float4*)&tile[r + ky][lane * 8 + 8];
        float4 u3 = *(const float4*)&tile[r + ky][lane * 8 + 12];
        win[0] = u0.x; win[1] = u0.y; win[2] = u0.z; win[3] = u0.w;
        win[4] = u1.x; win[5] = u1.y; win[6] = u1.z; win[7] = u1.w;
        win[8] = u2.x; win[9] = u2.y; win[10] = u2.z; win[11] = u2.w;
        win[12] = u3.x; win[13] = u3.y; win[14] = u3.z; win[15] = u3.w;
#pragma unroll
        for (int kx = 0; kx < 9; kx++) {
            float w0 = wsm[0][ky * 9 + kx];
            float w1 = wsm[1][ky * 9 + kx];
            float w2 = wsm[2][ky * 9 + kx];
#pragma unroll
            for (int p = 0; p < 8; p++) {
                float vi = win[p + kx];
                aq[p] += vi * w0;
                ak[p] += vi * w1;
                av[p] += vi * w2;
            }
        }
    }

    size_t o = (size_t)(b * C + c) * HW + (size_t)(y0 + r) * W + x0 + lane * 8;
    Pack8 qh, ql, kh, vh, vl;
#pragma unroll
    for (int p = 0; p < 8; p++) {
        __nv_bfloat16 h1 = __float2bfloat16(aq[p]);
        qh.h[p] = h1;
        ql.h[p] = __float2bfloat16(aq[p] - __bfloat162float(h1));
        kh.h[p] = __float2bfloat16(ak[p]);
        __nv_bfloat16 h3 = __float2bfloat16(av[p]);
        vh.h[p] = h3;
        vl.h[p] = __float2bfloat16(av[p] - __bfloat162float(h3));
    }
    *(uint4*)&g_qh[o] = qh.u;
    *(uint4*)&g_ql[o] = ql.u;
    *(uint4*)&g_kh[o] = kh.u;
    *(uint4*)&g_vh[o] = vh.u;
    *(uint4*)&g_vl[o] = vl.u;
}

// ---------------------------------------------------------------------------
// score_mma: S = (Q K^T)*SCALE per (b,h); 64x64 tiles, grid (4, B*NH).
// 2-term: Qhi*Khi + Qlo*Khi (K single-bf16; softmax absorbs ~1e-4 logit err).
// cp.async double-buffered K-loop, 3 tiles/buffer -> 4 CTAs/SM.
// ---------------------------------------------------------------------------
__global__ void __launch_bounds__(256) score_mma() {
    extern __shared__ char smem[];
    uint32_t sb = smem_u32(smem);
    const int tid = threadIdx.x;
    const int wid = tid >> 5, lane = tid & 31;
    const int bh = blockIdx.y;
    const int b = bh >> 3, h = bh & 7;
    const int quad = blockIdx.x;
    const int r0 = (quad >> 1) * 64, c0 = (quad & 1) * 64;
    const int wm = wid & 1;
    const int wn = wid >> 1;

    const uint4* qhp = (const uint4*)g_qh;
    const uint4* qlp = (const uint4*)g_ql;
    const uint4* khp = (const uint4*)g_kh;

    const size_t qb0 = ((size_t)(b * C + r0) * HW + h * D) >> 3;
    const size_t kb0 = ((size_t)(b * C + c0) * HW + h * D) >> 3;

    float acc[2][2][4];
#pragma unroll
    for (int mt = 0; mt < 2; mt++)
#pragma unroll
        for (int nt = 0; nt < 2; nt++)
#pragma unroll
            for (int j = 0; j < 4; j++) acc[mt][nt][j] = 0.0f;

    auto issue = [&](int chunk, int bufsel) {
        size_t qbase = qb0 + chunk * 8;   // 64 bf16 = 8 uint4
        size_t kbase = kb0 + chunk * 8;
        uint32_t bufo = sb + bufsel * SCB;
#pragma unroll
        for (int l = 0; l < 6; l++) {
            int i = tid + 256 * l;       // 0..1535
            int region = i >> 9, idx = i & 511;
            int row = idx >> 3, g = idx & 7;
            uint32_t dst = bufo + region * SCT + (uint32_t)row * LDT_S + g * 16;
            const uint4* src;
            if (region == 0)      src = qhp + qbase + (size_t)row * (HW / 8) + g;
            else if (region == 1) src = qlp + qbase + (size_t)row * (HW / 8) + g;
            else                  src = khp + kbase + (size_t)row * (HW / 8) + g;
            cp16(dst, src, true);
        }
        CP_COMMIT();
    };

    issue(0, 0);
    issue(1, 1);

    for (int t = 0; t < 32; t++) {
        if (t < 31) asm volatile("cp.async.wait_group 1;" ::: "memory");
        else        asm volatile("cp.async.wait_group 0;" ::: "memory");
        __syncthreads();

        uint32_t bufo = sb + (t & 1) * SCB;
#pragma unroll
        for (int ks = 0; ks < 4; ks++) {
            uint32_t ah[2][4], al[2][4], bh4[4];
#pragma unroll
            for (int mt = 0; mt < 2; mt++) {
                uint32_t addr = bufo
                    + (uint32_t)(wm * 32 + mt * 16 + (lane & 15)) * LDT_S
                    + (uint32_t)(ks * 16 + (lane >> 4) * 8) * 2;
                LDSM4(ah[mt], addr);
                LDSM4(al[mt], addr + SCT);
            }
            {
                int n = wn * 16 + (lane & 7) + ((lane >> 4) & 1) * 8;
                int ko = ks * 16 + ((lane >> 3) & 1) * 8;
                uint32_t addr = bufo + 2 * SCT + (uint32_t)n * LDT_S + (uint32_t)ko * 2;
                LDSM4(bh4, addr);
            }
#pragma unroll
            for (int mt = 0; mt < 2; mt++) {
#pragma unroll
                for (int nt = 0; nt < 2; nt++) {
                    int hf = nt * 2;
                    MMA_BF16(acc[mt][nt], ah[mt], bh4[hf], bh4[hf + 1]);
                    MMA_BF16(acc[mt][nt], al[mt], bh4[hf], bh4[hf + 1]);
                }
            }
        }
        __syncthreads();
        if (t + 2 < 32) issue(t + 2, t & 1);
    }

#pragma unroll
    for (int mt = 0; mt < 2; mt++) {
        int r = r0 + wm * 32 + mt * 16 + (lane >> 2);
#pragma unroll
        for (int nt = 0; nt < 2; nt++) {
            int cc = c0 + wn * 16 + nt * 8 + (lane & 3) * 2;
            *(float2*)&g_s[((size_t)bh * C + r) * C + cc] =
                make_float2(acc[mt][nt][0] * SCALE, acc[mt][nt][1] * SCALE);
            *(float2*)&g_s[((size_t)bh * C + r + 8) * C + cc] =
                make_float2(acc[mt][nt][2] * SCALE, acc[mt][nt][3] * SCALE);
        }
    }
}

// ---------------------------------------------------------------------------
// Row softmax over g_s; writes split bf16 P. One warp per row.
// ---------------------------------------------------------------------------
__global__ void softmax_p() {
    int gw = (blockIdx.x * blockDim.x + threadIdx.x) >> 5;
    int lane = threadIdx.x & 31;
    if (gw >= B * NH * C) return;
    float4 v = *(const float4*)&g_s[(size_t)gw * C + lane * 4];
    float m = fmaxf(fmaxf(v.x, v.y), fmaxf(v.z, v.w));
#pragma unroll
    for (int o = 16; o > 0; o >>= 1)
        m = fmaxf(m, __shfl_xor_sync(0xffffffffu, m, o));
    v.x = __expf(v.x - m);
    v.y = __expf(v.y - m);
    v.z = __expf(v.z - m);
    v.w = __expf(v.w - m);
    float s = v.x + v.y + v.z + v.w;
#pragma unroll
    for (int o = 16; o > 0; o >>= 1)
        s += __shfl_xor_sync(0xffffffffu, s, o);
    float inv = 1.0f / s;
    float p[4] = {v.x * inv, v.y * inv, v.z * inv, v.w * inv};

    Pack2 h0, h1, l0, l1;
#pragma unroll
    for (int j = 0; j < 4; j++) {
        __nv_bfloat16 hi = __float2bfloat16(p[j]);
        __nv_bfloat16 lo = __float2bfloat16(p[j] - __bfloat162float(hi));
        if (j < 2) { h0.h[j] = hi; l0.h[j] = lo; }
        else       { h1.h[j - 2] = hi; l1.h[j - 2] = lo; }
    }
    size_t base = (size_t)gw * C + lane * 4;
    *(uint32_t*)&g_ph[base]     = h0.u;
    *(uint32_t*)&g_ph[base + 2] = h1.u;
    *(uint32_t*)&g_pl[base]     = l0.u;
    *(uint32_t*)&g_pl[base + 2] = l1.u;
}

// ---------------------------------------------------------------------------
// pv_mma: out[pix][c] = sum_e V[e][pix] * P[c][e]. V staged in natural
// [e][pix] rows; A fragments via ldmatrix.trans (no v_transpose kernel).
// cp.async 2-phase staging (e-halves of 64). grid (16, B*NH).
// ---------------------------------------------------------------------------
__global__ void __launch_bounds__(256) pv_mma() {
    extern __shared__ char smem[];
    uint32_t sb = smem_u32(smem);
    const int tid = threadIdx.x;
    const int wid = tid >> 5, lane = tid & 31;
    const int bh = blockIdx.y;
    const int b = bh >> 3, h = bh & 7;
    const int dt = blockIdx.x * 128;
    const int wm = wid & 3;
    const int wn = wid >> 2;

    const uint4* vhp = (const uint4*)g_vh;
    const uint4* vlp = (const uint4*)g_vl;
    const uint4* php = (const uint4*)g_ph;
    const uint4* plp = (const uint4*)g_pl;

    // V row base: row e at g_vh[(b*C + e)*HW + h*D + dt], pix contiguous
    const size_t vrow = (size_t)b * C * (HW / 8) + ((h * D + dt) >> 3);
    const size_t bbase = (size_t)bh * C * C >> 3;

    auto issue_half = [&](int kh) {
#pragma unroll
        for (int l = 0; l < 16; l++) {
            int i = tid + 256 * l;           // 0..4095
            int region = i >> 10, idx = i & 1023;
            if (region < 2) {
                // A: V rows e = kh*64 + (0..63), 16 u4 per row (128 pix)
                int row = idx >> 4, g = idx & 15;
                int e = kh * 64 + row;
                uint32_t dst = sb + region * TILE_B2 + (uint32_t)e * LDT_B + g * 16;
                const uint4* src = (region == 0 ? vhp : vlp)
                    + vrow + (size_t)e * (HW / 8) + g;
                cp16(dst, src, true);
            } else {
                // B: P rows c = 0..127, e-half kh, 8 u4 per row
                int row = idx >> 3, g = idx & 7;
                uint32_t dst = sb + region * TILE_B2 + (uint32_t)row * LDT_B + kh * 128 + g * 16;
                const uint4* src = (region == 2 ? php : plp)
                    + bbase + (size_t)row * 16 + kh * 8 + g;
                cp16(dst, src, true);
            }
        }
        CP_COMMIT();
    };

    issue_half(0);
    issue_half(1);

    float acc[2][8][4];
#pragma unroll
    for (int mt = 0; mt < 2; mt++)
#pragma unroll
        for (int nt = 0; nt < 8; nt++)
#pragma unroll
            for (int j = 0; j < 4; j++) acc[mt][nt][j] = 0.0f;

#pragma unroll
    for (int half = 0; half < 2; half++) {
        if (half == 0) asm volatile("cp.async.wait_group 1;" ::: "memory");
        else           asm volatile("cp.async.wait_group 0;" ::: "memory");
        __syncthreads();

#pragma unroll
        for (int kss = 0; kss < 4; kss++) {
            int ks = half * 4 + kss;
            uint32_t ah[2][4], al[2][4], bh4[4][4], bl4[4][4];
#pragma unroll
            for (int mt = 0; mt < 2; mt++) {
                // trans-ldmatrix: rows = e (k), cols = pix (m)
                uint32_t addr = sb + SA_H
                    + (uint32_t)(ks * 16 + (lane & 7) + ((lane >> 4) & 1) * 8) * LDT_B
                    + (uint32_t)(wm * 32 + mt * 16 + ((lane >> 3) & 1) * 8) * 2;
                LDSM4_T(ah[mt], addr);
                LDSM4_T(al[mt], addr + TILE_B2);
            }
#pragma unroll
            for (int np = 0; np < 4; np++) {
                int n = wn * 64 + np * 16 + (lane & 7) + ((lane >> 4) & 1) * 8;
                int ko = ks * 16 + ((lane >> 3) & 1) * 8;
                uint32_t addr = sb + SB_H + (uint32_t)n * LDT_B + (uint32_t)ko * 2;
                LDSM4(bh4[np], addr);
                LDSM4(bl4[np], addr + TILE_B2);
            }
#pragma unroll
            for (int mt = 0; mt < 2; mt++) {
#pragma unroll
                for (int nt = 0; nt < 8; nt++) {
                    int np = nt >> 1, hf = (nt & 1) * 2;
                    MMA_BF16(acc[mt][nt], ah[mt], bh4[np][hf], bh4[np][hf + 1]);
                    MMA_BF16(acc[mt][nt], ah[mt], bl4[np][hf], bl4[np][hf + 1]);
                    MMA_BF16(acc[mt][nt], al[mt], bh4[np][hf], bh4[np][hf + 1]);
                }
            }
        }
    }

#pragma unroll
    for (int mt = 0; mt < 2; mt++) {
        size_t pix0 = (size_t)b * HW + h * D + dt + wm * 32 + mt * 16 + (lane >> 2);
#pragma unroll
        for (int nt = 0; nt < 8; nt++) {
            int c0 = wn * 64 + nt * 8 + (lane & 3) * 2;
            float a0 = acc[mt][nt][0], a1 = acc[mt][nt][1];
            float a2 = acc[mt][nt][2], a3 = acc[mt][nt][3];
            __nv_bfloat16 h0 = __float2bfloat16(a0);
            __nv_bfloat16 h1 = __float2bfloat16(a1);
            __nv_bfloat16 h2 = __float2bfloat16(a2);
            __nv_bfloat16 h3 = __float2bfloat16(a3);
            Pack2 ph0, pl0, ph1, pl1;
            ph0.h[0] = h0; ph0.h[1] = h1;
            pl0.h[0] = __float2bfloat16(a0 - __bfloat162float(h0));
            pl0.h[1] = __float2bfloat16(a1 - __bfloat162float(h1));
            ph1.h[0] = h2; ph1.h[1] = h3;
            pl1.h[0] = __float2bfloat16(a2 - __bfloat162float(h2));
            pl1.h[1] = __float2bfloat16(a3 - __bfloat162float(h3));
            *(uint32_t*)&g_ah[pix0 * C + c0]       = ph0.u;
            *(uint32_t*)&g_al[pix0 * C + c0]       = pl0.u;
            *(uint32_t*)&g_ah[(pix0 + 8) * C + c0] = ph1.u;
            *(uint32_t*)&g_al[(pix0 + 8) * C + c0] = pl1.u;
        }
    }
}

// ---------------------------------------------------------------------------
// out_conv: cp.async double-buffered pipeline (unchanged, near mma floor).
// ---------------------------------------------------------------------------
__global__ void __launch_bounds__(256) out_conv_mma(const float* __restrict__ bo,
                                                    float* __restrict__ out) {
    extern __shared__ char smem[];
    uint32_t sb = smem_u32(smem);
    const int tid = threadIdx.x;
    const int wid = tid >> 5, lane = tid & 31;
    const int y = blockIdx.x, b = blockIdx.y;
    const int wm = wid & 3;
    const int wn = wid >> 2;

    float acc[2][8][4];
#pragma unroll
    for (int mt = 0; mt < 2; mt++)
#pragma unroll
        for (int nt = 0; nt < 8; nt++)
#pragma unroll
            for (int j = 0; j < 4; j++) acc[mt][nt][j] = 0.0f;

    auto issue = [&](int t, int bufsel) {
        int tap = t >> 1, kh = t & 1;
        int dy = tap / 3, dx = tap % 3;
        int yy = y + dy - 1;
        bool yok = (unsigned)yy < (unsigned)H;
        int yc = yok ? yy : 0;
        uint32_t bufo = sb + bufsel * OC_BUF;
#pragma unroll
        for (int l = 0; l < 16; l++) {
            int i = tid + 256 * l;
            int region = i >> 10, idx = i & 1023;
            int row = idx >> 3, g = idx & 7;
            uint32_t daddr = bufo + region * OC_TILE + (uint32_t)row * LDT_S + g * 16;
            if (region < 2) {
                const __nv_bfloat16* src =
                    (region == 0 ? g_wh : g_wl) + (size_t)tap * (C * C) + row * C + kh * 64 + g * 8;
                cp16(daddr, src, true);
            } else {
                int xx = row + dx - 1;
                bool ok = yok && (unsigned)xx < (unsigned)W;
                int xc = ok ? xx : 0;
                const __nv_bfloat16* src =
                    (region == 2 ? g_ah : g_al)
                    + ((size_t)b * HW + yc * W + xc) * C + kh * 64 + g * 8;
                cp16(daddr, src, ok);
            }
        }
        CP_COMMIT();
    };

    issue(0, 0);
    issue(1, 1);

    for (int t = 0; t < 18; t++) {
        if (t < 17) asm volatile("cp.async.wait_group 1;" ::: "memory");
        else        asm volatile("cp.async.wait_group 0;" ::: "memory");
        __syncthreads();

        uint32_t bufo = sb + (t & 1) * OC_BUF;
#pragma unroll
        for (int ks = 0; ks < 4; ks++) {
            uint32_t ah[2][4], al[2][4], bh4[4][4], bl4[4][4];
#pragma unroll
            for (int mt = 0; mt < 2; mt++) {
                uint32_t addr = bufo
                    + (uint32_t)(wm * 32 + mt * 16 + (lane & 15)) * LDT_S
                    + (uint32_t)(ks * 16 + (lane >> 4) * 8) * 2;
                LDSM4(ah[mt], addr);
                LDSM4(al[mt], addr + OC_TILE);
            }
#pragma unroll
            for (int np = 0; np < 4; np++) {
                int n = wn * 64 + np * 16 + (lane & 7) + ((lane >> 4) & 1) * 8;
                int ko = ks * 16 + ((lane >> 3) & 1) * 8;
                uint32_t addr = bufo + 2 * OC_TILE + (uint32_t)n * LDT_S + (uint32_t)ko * 2;
                LDSM4(bh4[np], addr);
                LDSM4(bl4[np], addr + OC_TILE);
            }
#pragma unroll
            for (int mt = 0; mt < 2; mt++) {
#pragma unroll
                for (int nt = 0; nt < 8; nt++) {
                    int np = nt >> 1, hf = (nt & 1) * 2;
                    MMA_BF16(acc[mt][nt], ah[mt], bh4[np][hf], bh4[np][hf + 1]);
                    MMA_BF16(acc[mt][nt], ah[mt], bl4[np][hf], bl4[np][hf + 1]);
                    MMA_BF16(acc[mt][nt], al[mt], bh4[np][hf], bh4[np][hf + 1]);
                }
            }
        }
        __syncthreads();
        if (t + 2 < 18) issue(t + 2, t & 1);
    }

#pragma unroll
    for (int mt = 0; mt < 2; mt++) {
        int r0 = wm * 32 + mt * 16 + (lane >> 2);
        float bias0 = __ldg(bo + r0);
        float bias1 = __ldg(bo + r0 + 8);
        float* o0 = out + (size_t)(b * C + r0) * HW + (size_t)y * W;
        float* o1 = o0 + (size_t)8 * HW;
#pragma unroll
        for (int nt = 0; nt < 8; nt++) {
            int xc = wn * 64 + nt * 8 + (lane & 3) * 2;
            *(float2*)&o0[xc] = make_float2(acc[mt][nt][0] + bias0, acc[mt][nt][1] + bias0);
            *(float2*)&o1[xc] = make_float2(acc[mt][nt][2] + bias1, acc[mt][nt][3] + bias1);
        }
    }
}

// ---------------------------------------------------------------------------
extern "C" void kernel_launch(void* const* d_in, const int* in_sizes, int n_in,
                              void* d_out, int out_size) {
    const float* x  = (const float*)d_in[0];
    const float* wq = (const float*)d_in[1];
    const float* bq = (const float*)d_in[2];
    const float* wk = (const float*)d_in[3];
    const float* bk = (const float*)d_in[4];
    const float* wv = (const float*)d_in[5];
    const float* bv = (const float*)d_in[6];
    const float* wo = (const float*)d_in[7];
    const float* bo = (const float*)d_in[8];
    float* out = (float*)d_out;

    cudaFuncSetAttribute(score_mma,    cudaFuncAttributeMaxDynamicSharedMemorySize, SMEM_SCORE);
    cudaFuncSetAttribute(pv_mma,       cudaFuncAttributeMaxDynamicSharedMemorySize, SMEM_PV);
    cudaFuncSetAttribute(out_conv_mma, cudaFuncAttributeMaxDynamicSharedMemorySize, SMEM_OC);

    prep_w<<<(C * C * 9 + 255) / 256, 256>>>(wo);
    qkv_dwconv<<<dim3(W / 64, H / 32, B * C), 256>>>(x, wq, bq, wk, bk, wv, bv);
    score_mma<<<dim3(4, B * NH), 256, SMEM_SCORE>>>();
    softmax_p<<<(B * NH * C) / 8, 256>>>();
    pv_mma<<<dim3(HW / NH / 128, B * NH), 256, SMEM_PV>>>();
    out_conv_mma<<<dim3(H, B), 256, SMEM_OC>>>(bo, out);
}